// round 3
// baseline (speedup 1.0000x reference)
#include <cuda_runtime.h>

#define D   128   // LATDIM
#define A   64    // ANCHOR_SET_NUM
#define TN  96    // n-tile for main kernel (grid 105 <= 148 SMs, single wave)

// Scratch (allocation-free rule: __device__ globals)
__device__ float g_V[A * D];          // (1/A) * set_emb @ W1^T         [A][D]
__device__ float g_C[10000 * D];      // per-window constant            [T][D]
__device__ float g_S[10000 * D];      // chunk sums (g rows each)       [T][D]

// ---------------------------------------------------------------------------
// f32x2 packed helpers (sm_103a FFMA2 / packed add, PTX-only)
// ---------------------------------------------------------------------------
__device__ __forceinline__ unsigned long long pk2(float x, float y) {
    unsigned long long r;
    asm("mov.b64 %0, {%1, %2};" : "=l"(r) : "f"(x), "f"(y));
    return r;
}
__device__ __forceinline__ void unpk2(unsigned long long v, float& x, float& y) {
    asm("mov.b64 {%0, %1}, %2;" : "=f"(x), "=f"(y) : "l"(v));
}
__device__ __forceinline__ void ffma2(unsigned long long& a,
                                      unsigned long long b,
                                      unsigned long long c) {
    asm("fma.rn.f32x2 %0, %1, %2, %0;" : "+l"(a) : "l"(b), "l"(c));
}
__device__ __forceinline__ void fadd2(unsigned long long& a, unsigned long long b) {
    asm("add.rn.f32x2 %0, %0, %1;" : "+l"(a) : "l"(b));
}

// ---------------------------------------------------------------------------
// k_sums: S[t][k] = sum of g consecutive embed rows starting at g*t.
// Reads embeds exactly once. grid = ceil(T/2), 256 threads (2 t per block).
// ---------------------------------------------------------------------------
__global__ __launch_bounds__(256) void k_sums(const float* __restrict__ embeds,
                                              int T, int g) {
    const int t = blockIdx.x * 2 + (threadIdx.x >> 7);
    const int k = threadIdx.x & 127;
    if (t >= T) return;
    const float* p = embeds + (size_t)t * g * D + k;
    float s = 0.f;
    #pragma unroll 8
    for (int r = 0; r < g; r++) s += p[(size_t)r * D];
    g_S[(size_t)t * D + k] = s;
}

// ---------------------------------------------------------------------------
// k_cgemm: blocks [0, nConst) compute C tiles (16 t each);
//          blocks [nConst, nConst+4) compute V tiles (16 anchors each).
//   C[t][o] = (1/A) * sum_k E2[t][k] * W[o][D+k] + b[o],
//     E2[t][k] = sum_{c<step} S[(t+c) mod T][k]
//   V[a][o] = (1/A) * sum_k embeds[anchor[a]][k] * W[o][k]
// 512 threads. smem: XT[k][r] (x-tile transposed) + Wc[k][o] chunk.
// ---------------------------------------------------------------------------
__global__ __launch_bounds__(512) void k_cgemm(const float* __restrict__ embeds,
                                               const float* __restrict__ W,
                                               const float* __restrict__ b,
                                               const int*   __restrict__ anchor,
                                               int T, int step, int nConst) {
    __shared__ __align__(16) float XT[D][20];   // [k][r], pad 20 (16B-aligned rows)
    __shared__ float Wc[32][132];               // [k-chunk][o], pad 132

    const int tid = threadIdx.x;
    const bool isv = (blockIdx.x >= nConst);
    const int  base = isv ? (blockIdx.x - nConst) * 16 : blockIdx.x * 16;
    const int  R    = isv ? 16 : min(16, T - base);
    const int  woff = isv ? 0 : D;

    // ---- build XT[k][r] ----
    {
        const int k  = tid & 127;
        const int r0 = tid >> 7;   // 4 groups
        #pragma unroll
        for (int r = r0; r < 16; r += 4) {
            float val = 0.f;
            if (r < R) {
                if (isv) {
                    const int row = anchor[base + r];
                    val = embeds[(size_t)row * D + k];
                } else {
                    for (int c = 0; c < step; c++) {
                        int t = base + r + c;
                        if (t >= T) t -= T;
                        val += g_S[(size_t)t * D + k];
                    }
                }
            }
            XT[k][r] = val;
        }
    }

    // ---- GEMM: thread = (o, t-quad) ----
    const int o  = tid & 127;
    const int gq = tid >> 7;              // t-quad index 0..3
    unsigned long long acc0 = 0ull, acc1 = 0ull;   // t-pairs (4g,4g+1),(4g+2,4g+3)

    #pragma unroll
    for (int kc = 0; kc < 4; kc++) {
        __syncthreads();   // XT ready (kc=0) / previous Wc consumers done
        // stage Wc[k][o] for k in [kc*32, kc*32+32), transposed, coalesced LDG
        #pragma unroll
        for (int it = 0; it < 2; it++) {
            const int idx  = tid + it * 512;        // 0..1023
            const int orow = idx >> 3;
            const int kq   = (idx & 7) * 4;
            const float4 wv = *(const float4*)&W[(size_t)orow * (2 * D) + woff + kc * 32 + kq];
            Wc[kq + 0][orow] = wv.x;
            Wc[kq + 1][orow] = wv.y;
            Wc[kq + 2][orow] = wv.z;
            Wc[kq + 3][orow] = wv.w;
        }
        __syncthreads();

        #pragma unroll 8
        for (int kk = 0; kk < 32; kk++) {
            const float wv = Wc[kk][o];                       // dense, conflict-free
            const unsigned long long ww = pk2(wv, wv);
            const ulonglong2 x = *(const ulonglong2*)&XT[kc * 32 + kk][4 * gq];  // uniform
            ffma2(acc0, x.x, ww);
            ffma2(acc1, x.y, ww);
        }
    }

    // ---- epilogue ----
    float r0, r1, r2, r3;
    unpk2(acc0, r0, r1);
    unpk2(acc1, r2, r3);
    float res[4] = {r0, r1, r2, r3};
    const float bias = isv ? 0.f : b[o];

    #pragma unroll
    for (int i = 0; i < 4; i++) {
        const int rr = 4 * gq + i;
        if (rr < R) {
            const float v = res[i] * (1.0f / A) + bias;
            if (isv) g_V[(base + rr) * D + o] = v;
            else     g_C[(size_t)(base + rr) * D + o] = v;
        }
    }
}

// ---------------------------------------------------------------------------
// k_main: out[n][o] = sum_a dists[a][n] * V[a][o]  +  C[(step*n) mod T][o]
// 512 threads = 16 warps. warp w -> o-chunk [8w, 8w+8); lane l -> n in
// {n0+l, n0+l+32, n0+l+64}. V read uniformly from g_V (L1-resident);
// dists tile staged in smem (each element used once per lane but LDS dense).
// o-pairs packed in f32x2; v-pairs come free from 16B loads.
// ---------------------------------------------------------------------------
__global__ __launch_bounds__(512) void k_main(const float* __restrict__ dists,
                                              float* __restrict__ out,
                                              int N, int T, int step) {
    __shared__ float sd[A][TN];   // 24 KB

    const int tid = threadIdx.x;
    const int n0  = blockIdx.x * TN;

    // stage dists tile (zero-padded tail)
    #pragma unroll
    for (int i = tid; i < A * TN / 4; i += 512) {
        const int a  = i / (TN / 4);
        const int j4 = (i % (TN / 4)) * 4;
        const int n  = n0 + j4;
        const float* src = dists + (size_t)a * N + n;
        float4 v;
        if (n + 3 < N) {
            v = *(const float4*)src;
        } else {
            v.x = (n + 0 < N) ? src[0] : 0.f;
            v.y = (n + 1 < N) ? src[1] : 0.f;
            v.z = (n + 2 < N) ? src[2] : 0.f;
            v.w = (n + 3 < N) ? src[3] : 0.f;
        }
        ((float4*)sd)[i] = v;
    }
    __syncthreads();

    const int w  = tid >> 5;
    const int l  = tid & 31;
    const int ob = w * 8;

    unsigned long long acc[3][4];
    #pragma unroll
    for (int i = 0; i < 3; i++)
        #pragma unroll
        for (int j = 0; j < 4; j++) acc[i][j] = 0ull;

    #pragma unroll 8
    for (int a = 0; a < A; a++) {
        // v: uniform 16B global loads (L1 hit after warm), pairs free
        const ulonglong2 v01 = *(const ulonglong2*)&g_V[a * D + ob];
        const ulonglong2 v23 = *(const ulonglong2*)&g_V[a * D + ob + 4];
        // d: dense conflict-free smem loads
        const float d0 = sd[a][l];
        const float d1 = sd[a][l + 32];
        const float d2 = sd[a][l + 64];
        const unsigned long long dd0 = pk2(d0, d0);
        const unsigned long long dd1 = pk2(d1, d1);
        const unsigned long long dd2 = pk2(d2, d2);

        ffma2(acc[0][0], dd0, v01.x); ffma2(acc[0][1], dd0, v01.y);
        ffma2(acc[0][2], dd0, v23.x); ffma2(acc[0][3], dd0, v23.y);
        ffma2(acc[1][0], dd1, v01.x); ffma2(acc[1][1], dd1, v01.y);
        ffma2(acc[1][2], dd1, v23.x); ffma2(acc[1][3], dd1, v23.y);
        ffma2(acc[2][0], dd2, v01.x); ffma2(acc[2][1], dd2, v01.y);
        ffma2(acc[2][2], dd2, v23.x); ffma2(acc[2][3], dd2, v23.y);
    }

    // epilogue: add C row, store (packed adds, no unpacking)
    #pragma unroll
    for (int ni = 0; ni < 3; ni++) {
        const int n = n0 + l + 32 * ni;
        if (n < N) {
            const int t = (step * n) % T;
            const ulonglong2 c0 = *(const ulonglong2*)&g_C[(size_t)t * D + ob];
            const ulonglong2 c1 = *(const ulonglong2*)&g_C[(size_t)t * D + ob + 4];
            fadd2(acc[ni][0], c0.x); fadd2(acc[ni][1], c0.y);
            fadd2(acc[ni][2], c1.x); fadd2(acc[ni][3], c1.y);
            ulonglong2 r0; r0.x = acc[ni][0]; r0.y = acc[ni][1];
            ulonglong2 r1; r1.x = acc[ni][2]; r1.y = acc[ni][3];
            *(ulonglong2*)&out[(size_t)n * D + ob]     = r0;
            *(ulonglong2*)&out[(size_t)n * D + ob + 4] = r1;
        }
    }
}

// ---------------------------------------------------------------------------
extern "C" void kernel_launch(void* const* d_in, const int* in_sizes, int n_in,
                              void* d_out, int out_size) {
    const float* embeds = (const float*)d_in[0];   // [N, 128]
    const float* dists  = (const float*)d_in[1];   // [64, N]
    const float* W      = (const float*)d_in[2];   // [128, 256]
    const float* b      = (const float*)d_in[3];   // [128]
    const int*   anchor = (const int*)  d_in[4];   // [64] int32
    float* out = (float*)d_out;

    const int N = in_sizes[0] / D;                 // 10000

    // g = gcd(A, N); T = N/g distinct windows; t(n) = (A/g * n) mod T
    int g = A, y = N;
    while (y) { int r = g % y; g = y; y = r; }
    const int T    = N / g;       // 625
    const int step = A / g;       // 4

    const int nConst = (T + 15) / 16;              // 40

    k_sums <<<(T + 1) / 2, 256>>>(embeds, T, g);
    k_cgemm<<<nConst + A / 16, 512>>>(embeds, W, b, anchor, T, step, nConst);
    k_main <<<(N + TN - 1) / TN, 512>>>(dists, out, N, T, step);
}